// round 11
// baseline (speedup 1.0000x reference)
#include <cuda_runtime.h>
#include <cuda_bf16.h>
#include <math.h>

#define B_SZ   16
#define C_IN   64
#define HH     256
#define WW     256
#define CKK    576
#define FC_DIM 512
#define IMG_PIX (HH * WW)
#define N_IMG  (B_SZ * C_IN)
#define FOUT_ELEMS ((size_t)N_IMG * IMG_PIX)

#define MLP_BLOCKS 81
#define CONV_BLOCKS 8192
#define TOTAL_BLOCKS (MLP_BLOCKS + CONV_BLOCKS)

// Partials (deterministic fixed-order summation)
__device__ float g_p1[8][B_SZ * CKK];
__device__ float g_p2[9][B_SZ * CKK];
__device__ float g_kw[B_SZ * CKK];
__device__ unsigned int g_c1, g_c2, g_c3;   // MLP barrier counters
__device__ unsigned int g_sm_cnt;           // softmax completion counter
__device__ unsigned int g_ready;            // weights-ready flag
__device__ unsigned int g_conv_done;        // conv completion counter

__device__ __forceinline__ void mlp_barrier(unsigned int* cnt, unsigned int* rst) {
    __threadfence();
    __syncthreads();
    if (threadIdx.x == 0) {
        unsigned int old = atomicAdd(cnt, 1u);
        if (rst && old == MLP_BLOCKS - 1u) *rst = 0u;
        while (__ldcg(cnt) < MLP_BLOCKS) __nanosleep(20);
    }
    __syncthreads();
    __threadfence();
}

#define ROWS_PER_BLOCK 32
#define ROWS_PER_THREAD 8

__device__ __forceinline__ void load_row6(
    const float* __restrict__ img, int gr, int tx, float* __restrict__ w)
{
    gr = (gr < 0) ? 1 : ((gr > HH - 1) ? (2 * HH - 2 - gr) : gr);
    const float* rowp = img + gr * WW;
    const float4 q = __ldg((const float4*)rowp + tx);
    w[1] = q.x; w[2] = q.y; w[3] = q.z; w[4] = q.w;
    w[0] = (tx == 0)      ? q.y : __ldg(rowp + 4 * tx - 1);
    w[5] = (tx == WW/4-1) ? q.z : __ldg(rowp + 4 * tx + 4);
}

// ---------------------------------------------------------------------------
// ONE kernel. bid < 81: MLP (verified R10 structure) -> sets g_ready.
//             bid >= 81: conv (prefetch, spin on flag, __ldcg weights, compute).
// ---------------------------------------------------------------------------
__global__ __launch_bounds__(256, 8) void EKG_fused(
    const float* __restrict__ Fd,
    const float* __restrict__ Fc,
    const float* __restrict__ W1, const float* __restrict__ b1,
    const float* __restrict__ W2, const float* __restrict__ b2,
    float* __restrict__ out,
    float* __restrict__ kw_tail, int write_tail)
{
    const int bid = blockIdx.x;
    const int tid = threadIdx.x;

    if (bid < MLP_BLOCKS) {
        // ================= MLP path (verified structure) =================
        __shared__ float sfc[16 * 64];
        __shared__ float srd[4 * 64 * 16];
        __shared__ float red[8];
        __shared__ float bcast;

        const int tx  = tid & 63;
        const int ty  = tid >> 6;
        const int lane = tid & 31;
        const int wid  = tid >> 5;

        // ---- Phase 1 ----
        if (bid < 72) {
            const int jt = bid / 8, ic = bid % 8;
            const int i0 = ic * 64;
            const int j  = jt * 64 + tx;

            for (int q = tid; q < 16 * 64; q += 256) {
                const int b = q >> 6, il = q & 63;
                sfc[q] = Fc[b * FC_DIM + i0 + il];
            }
            __syncthreads();

            float w[16];
            const float* __restrict__ wp = W1 + (size_t)(i0 + ty * 16) * CKK + j;
            #pragma unroll
            for (int k = 0; k < 16; ++k) w[k] = __ldg(wp + k * CKK);

            float acc[16];
            #pragma unroll
            for (int b = 0; b < 16; ++b) acc[b] = 0.f;
            #pragma unroll
            for (int k = 0; k < 16; ++k) {
                const int il = ty * 16 + k;
                #pragma unroll
                for (int b = 0; b < 16; ++b)
                    acc[b] = fmaf(sfc[b * 64 + il], w[k], acc[b]);
            }
            #pragma unroll
            for (int b = 0; b < 16; ++b) srd[(ty * 64 + tx) * 16 + b] = acc[b];
            __syncthreads();

            for (int q = tid; q < 1024; q += 256) {
                const int jj = q >> 4, b = q & 15;
                float v = ((srd[(jj) * 16 + b]       + srd[(64 + jj) * 16 + b]) +
                           (srd[(128 + jj) * 16 + b] + srd[(192 + jj) * 16 + b]));
                if (ic == 0) v += b1[jt * 64 + jj];
                g_p1[ic][b * CKK + jt * 64 + jj] = v;
            }
        }

        mlp_barrier(&g_c1, 0);

        // ---- Phase 2 ----
        {
            const int jt = bid / 9, ic = bid % 9;
            const int i0 = ic * 64;
            const int j  = jt * 64 + tx;

            for (int q = tid; q < 16 * 64; q += 256) {
                const int b = q >> 6, il = q & 63;
                const int idx = b * CKK + i0 + il;
                float h = (((g_p1[0][idx] + g_p1[1][idx]) + (g_p1[2][idx] + g_p1[3][idx])) +
                           ((g_p1[4][idx] + g_p1[5][idx]) + (g_p1[6][idx] + g_p1[7][idx])));
                sfc[q] = fmaxf(h, 0.0f);
            }
            __syncthreads();

            float w[16];
            const float* __restrict__ wp = W2 + (size_t)(i0 + ty * 16) * CKK + j;
            #pragma unroll
            for (int k = 0; k < 16; ++k) w[k] = __ldg(wp + k * CKK);

            float acc[16];
            #pragma unroll
            for (int b = 0; b < 16; ++b) acc[b] = 0.f;
            #pragma unroll
            for (int k = 0; k < 16; ++k) {
                const int il = ty * 16 + k;
                #pragma unroll
                for (int b = 0; b < 16; ++b)
                    acc[b] = fmaf(sfc[b * 64 + il], w[k], acc[b]);
            }
            __syncthreads();
            #pragma unroll
            for (int b = 0; b < 16; ++b) srd[(ty * 64 + tx) * 16 + b] = acc[b];
            __syncthreads();

            for (int q = tid; q < 1024; q += 256) {
                const int jj = q >> 4, b = q & 15;
                float v = ((srd[(jj) * 16 + b]       + srd[(64 + jj) * 16 + b]) +
                           (srd[(128 + jj) * 16 + b] + srd[(192 + jj) * 16 + b]));
                if (ic == 0) v += b2[jt * 64 + jj];
                g_p2[ic][b * CKK + jt * 64 + jj] = v;
            }
        }

        mlp_barrier(&g_c2, &g_c1);

        // ---- Phase 3: softmax (blocks 0..15) ----
        if (bid < B_SZ) {
            const int b = bid;
            float lg[3];
            float lmax = -INFINITY;
            #pragma unroll
            for (int t = 0; t < 3; ++t) {
                if (t < 2 || tid < 64) {
                    const int idx = b * CKK + tid + 256 * t;
                    float v = (((g_p2[0][idx] + g_p2[1][idx]) + (g_p2[2][idx] + g_p2[3][idx])) +
                               ((g_p2[4][idx] + g_p2[5][idx]) + (g_p2[6][idx] + g_p2[7][idx])) +
                               g_p2[8][idx]);
                    lg[t] = v;
                    lmax = fmaxf(lmax, v);
                } else lg[t] = -INFINITY;
            }
            #pragma unroll
            for (int o = 16; o > 0; o >>= 1)
                lmax = fmaxf(lmax, __shfl_xor_sync(0xffffffffu, lmax, o));
            if (lane == 0) red[wid] = lmax;
            __syncthreads();
            if (wid == 0) {
                float v = (lane < 8) ? red[lane] : -INFINITY;
                #pragma unroll
                for (int o = 4; o > 0; o >>= 1)
                    v = fmaxf(v, __shfl_xor_sync(0xffffffffu, v, o));
                if (lane == 0) bcast = v;
            }
            __syncthreads();
            const float maxv = bcast;

            float e[3];
            float lsum = 0.f;
            #pragma unroll
            for (int t = 0; t < 3; ++t) {
                e[t] = (t < 2 || tid < 64) ? expf(lg[t] - maxv) : 0.0f;
                lsum += e[t];
            }
            #pragma unroll
            for (int o = 16; o > 0; o >>= 1)
                lsum += __shfl_xor_sync(0xffffffffu, lsum, o);
            __syncthreads();
            if (lane == 0) red[wid] = lsum;
            __syncthreads();
            if (wid == 0) {
                float v = (lane < 8) ? red[lane] : 0.0f;
                #pragma unroll
                for (int o = 4; o > 0; o >>= 1)
                    v += __shfl_xor_sync(0xffffffffu, v, o);
                if (lane == 0) bcast = v;
            }
            __syncthreads();
            const float inv = 1.0f / bcast;

            #pragma unroll
            for (int t = 0; t < 3; ++t) {
                if (t < 2 || tid < 64) {
                    const int idx = b * CKK + tid + 256 * t;
                    const float kw = e[t] * inv;
                    g_kw[idx] = kw;
                    if (write_tail) kw_tail[idx] = kw;
                }
            }

            // signal: 16th softmax block sets the flag (after fencing writes to L2)
            __threadfence();
            __syncthreads();
            if (tid == 0) {
                unsigned int old = atomicAdd(&g_sm_cnt, 1u);
                if (old == B_SZ - 1u) atomicExch(&g_ready, 1u);
            }
        }

        // MLP exit: last arriver resets c2, c3
        __threadfence();
        __syncthreads();
        if (tid == 0) {
            unsigned int old = atomicAdd(&g_c3, 1u);
            if (old == MLP_BLOCKS - 1u) { g_c2 = 0u; g_c3 = 0u; __threadfence(); }
        }
        return;
    }

    // ================= conv path =================
    const int cid = bid - MLP_BLOCKS;
    const int bx  = cid & 7;
    const int bc  = cid >> 3;
    const int tx  = tid & 63;
    const int ty  = tid >> 6;
    const int rbase = bx * ROWS_PER_BLOCK + ty * ROWS_PER_THREAD;

    const float* __restrict__ img = Fd  + (size_t)bc * IMG_PIX;
    float*       __restrict__ o   = out + (size_t)bc * IMG_PIX;

    // prefetch first two window rows (weight-independent)
    float win[3][6];
    load_row6(img, rbase - 1, tx, win[0]);
    load_row6(img, rbase + 0, tx, win[1]);

    // spin until weights are published (L2-coherent reads only)
    if (tid == 0) {
        while (__ldcg(&g_ready) == 0u) __nanosleep(64);
    }
    __syncthreads();   // all threads ordered after the flag observation

    // weights via __ldcg: L2-coherent, cannot be treated as kernel-constant
    const float* kwp = g_kw + bc * 9;
    const float w00 = __ldcg(kwp+0), w01 = __ldcg(kwp+1), w02 = __ldcg(kwp+2);
    const float w10 = __ldcg(kwp+3), w11 = __ldcg(kwp+4), w12 = __ldcg(kwp+5);
    const float w20 = __ldcg(kwp+6), w21 = __ldcg(kwp+7), w22 = __ldcg(kwp+8);

    #pragma unroll
    for (int rr = 0; rr < ROWS_PER_THREAD; ++rr) {
        load_row6(img, rbase + rr + 1, tx, win[(rr + 2) % 3]);

        const float* T  = win[rr % 3];
        const float* M  = win[(rr + 1) % 3];
        const float* Bt = win[(rr + 2) % 3];

        float4 r;
        r.x = w00*T[0]; r.x = fmaf(w01,T[1],r.x); r.x = fmaf(w02,T[2],r.x);
        r.x = fmaf(w10,M[0],r.x); r.x = fmaf(w11,M[1],r.x); r.x = fmaf(w12,M[2],r.x);
        r.x = fmaf(w20,Bt[0],r.x); r.x = fmaf(w21,Bt[1],r.x); r.x = fmaf(w22,Bt[2],r.x);

        r.y = w00*T[1]; r.y = fmaf(w01,T[2],r.y); r.y = fmaf(w02,T[3],r.y);
        r.y = fmaf(w10,M[1],r.y); r.y = fmaf(w11,M[2],r.y); r.y = fmaf(w12,M[3],r.y);
        r.y = fmaf(w20,Bt[1],r.y); r.y = fmaf(w21,Bt[2],r.y); r.y = fmaf(w22,Bt[3],r.y);

        r.z = w00*T[2]; r.z = fmaf(w01,T[3],r.z); r.z = fmaf(w02,T[4],r.z);
        r.z = fmaf(w10,M[2],r.z); r.z = fmaf(w11,M[3],r.z); r.z = fmaf(w12,M[4],r.z);
        r.z = fmaf(w20,Bt[2],r.z); r.z = fmaf(w21,Bt[3],r.z); r.z = fmaf(w22,Bt[4],r.z);

        r.w = w00*T[3]; r.w = fmaf(w01,T[4],r.w); r.w = fmaf(w02,T[5],r.w);
        r.w = fmaf(w10,M[3],r.w); r.w = fmaf(w11,M[4],r.w); r.w = fmaf(w12,M[5],r.w);
        r.w = fmaf(w20,Bt[3],r.w); r.w = fmaf(w21,Bt[4],r.w); r.w = fmaf(w22,Bt[5],r.w);

        __stcs((float4*)(o + (size_t)(rbase + rr) * WW + 4 * tx), r);
    }

    // last conv block resets flags for next graph replay
    if (tid == 0) {
        unsigned int old = atomicAdd(&g_conv_done, 1u);
        if (old == CONV_BLOCKS - 1u) {
            g_ready = 0u; g_sm_cnt = 0u; g_conv_done = 0u;
            __threadfence();
        }
    }
}

// ---------------------------------------------------------------------------
extern "C" void kernel_launch(void* const* d_in, const int* in_sizes, int n_in,
                              void* d_out, int out_size) {
    const float* Fd = (const float*)d_in[0];
    const float* Fc = (const float*)d_in[1];
    const float* W1 = (const float*)d_in[2];
    const float* b1 = (const float*)d_in[3];
    const float* W2 = (const float*)d_in[4];
    const float* b2 = (const float*)d_in[5];
    float* out = (float*)d_out;

    const int write_tail = ((size_t)out_size >= FOUT_ELEMS + (size_t)B_SZ * CKK) ? 1 : 0;
    float* kw_tail = out + FOUT_ELEMS;

    EKG_fused<<<TOTAL_BLOCKS, 256>>>(Fd, Fc, W1, b1, W2, b2, out, kw_tail, write_tail);
}

// round 12
// speedup vs baseline: 1.3623x; 1.3623x over previous
#include <cuda_runtime.h>
#include <cuda_bf16.h>
#include <math.h>

#define B_SZ   16
#define C_IN   64
#define HH     256
#define WW     256
#define CKK    576
#define FC_DIM 512
#define IMG_PIX (HH * WW)
#define N_IMG  (B_SZ * C_IN)
#define FOUT_ELEMS ((size_t)N_IMG * IMG_PIX)

#define MLP_BLOCKS 81
#define CONV_BLOCKS 8192
#define TOTAL_BLOCKS (MLP_BLOCKS + CONV_BLOCKS)

// Partials (deterministic fixed-order summation)
__device__ float g_p1[8][B_SZ * CKK];   // layer1 partials per 64-i-chunk (ic0 includes b1)
__device__ float g_p2[9][B_SZ * CKK];   // layer2 partials per 64-i-chunk (ic0 includes b2)
__device__ float g_kw[B_SZ * CKK];      // softmaxed kernel weights

// Control counters: each on its OWN 128B line (no false sharing).
struct __align__(128) PadCtr { unsigned int v; unsigned int pad[31]; };
__device__ PadCtr g_c1, g_c2, g_c3;     // MLP barrier counters
__device__ PadCtr g_sm;                 // softmax completion counter
__device__ PadCtr g_ready;              // weights-ready flag
__device__ PadCtr g_done;               // conv completion counter

__device__ __forceinline__ void mlp_barrier(PadCtr* cnt, PadCtr* rst) {
    __threadfence();
    __syncthreads();
    if (threadIdx.x == 0) {
        unsigned int old = atomicAdd(&cnt->v, 1u);
        if (rst && old == MLP_BLOCKS - 1u) rst->v = 0u;
        while (__ldcg(&cnt->v) < MLP_BLOCKS) __nanosleep(20);
    }
    __syncthreads();
    __threadfence();
}

#define ROWS_PER_BLOCK 32
#define ROWS_PER_THREAD 8

__device__ __forceinline__ void load_row6(
    const float* __restrict__ img, int gr, int tx, float* __restrict__ w)
{
    gr = (gr < 0) ? 1 : ((gr > HH - 1) ? (2 * HH - 2 - gr) : gr);
    const float* rowp = img + gr * WW;
    const float4 q = __ldg((const float4*)rowp + tx);
    w[1] = q.x; w[2] = q.y; w[3] = q.z; w[4] = q.w;
    w[0] = (tx == 0)      ? q.y : __ldg(rowp + 4 * tx - 1);
    w[5] = (tx == WW/4-1) ? q.z : __ldg(rowp + 4 * tx + 4);
}

// ---------------------------------------------------------------------------
// ONE kernel. bid < 81: MLP -> sets g_ready. bid >= 81: conv.
// MLP smem footprint kept to ~8.3KB so conv blocks keep a large L1D carveout.
// ---------------------------------------------------------------------------
__global__ __launch_bounds__(256, 8) void EKG_fused(
    const float* __restrict__ Fd,
    const float* __restrict__ Fc,
    const float* __restrict__ W1, const float* __restrict__ b1,
    const float* __restrict__ W2, const float* __restrict__ b2,
    float* __restrict__ out,
    float* __restrict__ kw_tail, int write_tail)
{
    const int bid = blockIdx.x;
    const int tid = threadIdx.x;

    if (bid < MLP_BLOCKS) {
        // ================= MLP path =================
        __shared__ float sfc[16 * 64];   // 4KB: input / hidden slice [b][il]
        __shared__ float srd[1024];      // 4KB: per-group reduction buffer
        __shared__ float red[8];
        __shared__ float bcast;

        const int tx  = tid & 63;        // j within 64-tile
        const int ty  = tid >> 6;        // i sub-chunk (16-deep)
        const int lane = tid & 31;
        const int wid  = tid >> 5;
        const int jj  = tid >> 2;        // reduction: j-local
        const int b4  = tid & 3;         // reduction: batch within group

        // ---- Phase 1: layer1 partials (blocks 0..71; jt 0..8, ic 0..7) ----
        if (bid < 72) {
            const int jt = bid / 8, ic = bid % 8;
            const int i0 = ic * 64;
            const int j  = jt * 64 + tx;

            for (int q = tid; q < 1024; q += 256) {
                const int b = q >> 6, il = q & 63;
                sfc[q] = Fc[b * FC_DIM + i0 + il];
            }
            __syncthreads();

            float w[16];
            const float* __restrict__ wp = W1 + (size_t)(i0 + ty * 16) * CKK + j;
            #pragma unroll
            for (int k = 0; k < 16; ++k) w[k] = __ldg(wp + k * CKK);

            #pragma unroll
            for (int g = 0; g < 4; ++g) {
                float a0 = 0.f, a1 = 0.f, a2 = 0.f, a3 = 0.f;
                #pragma unroll
                for (int k = 0; k < 16; ++k) {
                    const float wv = w[k];
                    const int il = ty * 16 + k;
                    a0 = fmaf(sfc[(g * 4 + 0) * 64 + il], wv, a0);
                    a1 = fmaf(sfc[(g * 4 + 1) * 64 + il], wv, a1);
                    a2 = fmaf(sfc[(g * 4 + 2) * 64 + il], wv, a2);
                    a3 = fmaf(sfc[(g * 4 + 3) * 64 + il], wv, a3);
                }
                const int base = (ty * 64 + tx) * 4;
                srd[base + 0] = a0; srd[base + 1] = a1;
                srd[base + 2] = a2; srd[base + 3] = a3;
                __syncthreads();
                {
                    float v = ((srd[jj * 4 + b4]       + srd[256 + jj * 4 + b4]) +
                               (srd[512 + jj * 4 + b4] + srd[768 + jj * 4 + b4]));
                    if (ic == 0) v += b1[jt * 64 + jj];
                    g_p1[ic][(g * 4 + b4) * CKK + jt * 64 + jj] = v;
                }
                __syncthreads();
            }
        }

        mlp_barrier(&g_c1, 0);

        // ---- Phase 2: layer2 partials (all 81; jt 0..8, ic 0..8) ----
        {
            const int jt = bid / 9, ic = bid % 9;
            const int i0 = ic * 64;
            const int j  = jt * 64 + tx;

            for (int q = tid; q < 1024; q += 256) {
                const int b = q >> 6, il = q & 63;
                const int idx = b * CKK + i0 + il;
                float h = (((g_p1[0][idx] + g_p1[1][idx]) + (g_p1[2][idx] + g_p1[3][idx])) +
                           ((g_p1[4][idx] + g_p1[5][idx]) + (g_p1[6][idx] + g_p1[7][idx])));
                sfc[q] = fmaxf(h, 0.0f);
            }
            __syncthreads();

            float w[16];
            const float* __restrict__ wp = W2 + (size_t)(i0 + ty * 16) * CKK + j;
            #pragma unroll
            for (int k = 0; k < 16; ++k) w[k] = __ldg(wp + k * CKK);

            #pragma unroll
            for (int g = 0; g < 4; ++g) {
                float a0 = 0.f, a1 = 0.f, a2 = 0.f, a3 = 0.f;
                #pragma unroll
                for (int k = 0; k < 16; ++k) {
                    const float wv = w[k];
                    const int il = ty * 16 + k;
                    a0 = fmaf(sfc[(g * 4 + 0) * 64 + il], wv, a0);
                    a1 = fmaf(sfc[(g * 4 + 1) * 64 + il], wv, a1);
                    a2 = fmaf(sfc[(g * 4 + 2) * 64 + il], wv, a2);
                    a3 = fmaf(sfc[(g * 4 + 3) * 64 + il], wv, a3);
                }
                const int base = (ty * 64 + tx) * 4;
                srd[base + 0] = a0; srd[base + 1] = a1;
                srd[base + 2] = a2; srd[base + 3] = a3;
                __syncthreads();
                {
                    float v = ((srd[jj * 4 + b4]       + srd[256 + jj * 4 + b4]) +
                               (srd[512 + jj * 4 + b4] + srd[768 + jj * 4 + b4]));
                    if (ic == 0) v += b2[jt * 64 + jj];
                    g_p2[ic][(g * 4 + b4) * CKK + jt * 64 + jj] = v;
                }
                __syncthreads();
            }
        }

        mlp_barrier(&g_c2, &g_c1);   // last arriver resets c1 for next replay

        // ---- Phase 3: softmax (blocks 0..15) ----
        if (bid < B_SZ) {
            const int b = bid;
            float lg[3];
            float lmax = -INFINITY;
            #pragma unroll
            for (int t = 0; t < 3; ++t) {
                if (t < 2 || tid < 64) {
                    const int idx = b * CKK + tid + 256 * t;
                    float v = ((((g_p2[0][idx] + g_p2[1][idx]) + (g_p2[2][idx] + g_p2[3][idx])) +
                                ((g_p2[4][idx] + g_p2[5][idx]) + (g_p2[6][idx] + g_p2[7][idx]))) +
                               g_p2[8][idx]);
                    lg[t] = v;
                    lmax = fmaxf(lmax, v);
                } else lg[t] = -INFINITY;
            }
            #pragma unroll
            for (int o = 16; o > 0; o >>= 1)
                lmax = fmaxf(lmax, __shfl_xor_sync(0xffffffffu, lmax, o));
            if (lane == 0) red[wid] = lmax;
            __syncthreads();
            if (wid == 0) {
                float v = (lane < 8) ? red[lane] : -INFINITY;
                #pragma unroll
                for (int o = 4; o > 0; o >>= 1)
                    v = fmaxf(v, __shfl_xor_sync(0xffffffffu, v, o));
                if (lane == 0) bcast = v;
            }
            __syncthreads();
            const float maxv = bcast;

            float e[3];
            float lsum = 0.f;
            #pragma unroll
            for (int t = 0; t < 3; ++t) {
                e[t] = (t < 2 || tid < 64) ? expf(lg[t] - maxv) : 0.0f;
                lsum += e[t];
            }
            #pragma unroll
            for (int o = 16; o > 0; o >>= 1)
                lsum += __shfl_xor_sync(0xffffffffu, lsum, o);
            __syncthreads();
            if (lane == 0) red[wid] = lsum;
            __syncthreads();
            if (wid == 0) {
                float v = (lane < 8) ? red[lane] : 0.0f;
                #pragma unroll
                for (int o = 4; o > 0; o >>= 1)
                    v += __shfl_xor_sync(0xffffffffu, v, o);
                if (lane == 0) bcast = v;
            }
            __syncthreads();
            const float inv = 1.0f / bcast;

            #pragma unroll
            for (int t = 0; t < 3; ++t) {
                if (t < 2 || tid < 64) {
                    const int idx = b * CKK + tid + 256 * t;
                    const float kw = e[t] * inv;
                    g_kw[idx] = kw;
                    if (write_tail) kw_tail[idx] = kw;
                }
            }

            __threadfence();
            __syncthreads();
            if (tid == 0) {
                unsigned int old = atomicAdd(&g_sm.v, 1u);
                if (old == B_SZ - 1u) atomicExch(&g_ready.v, 1u);
            }
        }

        // MLP exit: last arriver resets c2, c3
        __threadfence();
        __syncthreads();
        if (tid == 0) {
            unsigned int old = atomicAdd(&g_c3.v, 1u);
            if (old == MLP_BLOCKS - 1u) { g_c2.v = 0u; g_c3.v = 0u; __threadfence(); }
        }
        return;
    }

    // ================= conv path =================
    const int cid = bid - MLP_BLOCKS;
    const int bx  = cid & 7;
    const int bc  = cid >> 3;
    const int tx  = tid & 63;
    const int ty  = tid >> 6;
    const int rbase = bx * ROWS_PER_BLOCK + ty * ROWS_PER_THREAD;

    const float* __restrict__ img = Fd  + (size_t)bc * IMG_PIX;
    float*       __restrict__ o   = out + (size_t)bc * IMG_PIX;

    // prefetch first two window rows into registers (weight-independent)
    float win[3][6];
    load_row6(img, rbase - 1, tx, win[0]);
    load_row6(img, rbase + 0, tx, win[1]);

    // warm L2 with the remaining rows while (possibly) waiting for weights
    #pragma unroll
    for (int rr = 1; rr <= ROWS_PER_THREAD; ++rr) {
        int gr = rbase + rr;
        gr = (gr > HH - 1) ? (2 * HH - 2 - gr) : gr;
        const float* p = img + gr * WW + 4 * tx;
        asm volatile("prefetch.global.L2 [%0];" :: "l"(p));
    }

    if (tid == 0) {
        while (__ldcg(&g_ready.v) == 0u) __nanosleep(256);
    }
    __syncthreads();

    const float* kwp = g_kw + bc * 9;
    const float w00 = __ldcg(kwp+0), w01 = __ldcg(kwp+1), w02 = __ldcg(kwp+2);
    const float w10 = __ldcg(kwp+3), w11 = __ldcg(kwp+4), w12 = __ldcg(kwp+5);
    const float w20 = __ldcg(kwp+6), w21 = __ldcg(kwp+7), w22 = __ldcg(kwp+8);

    #pragma unroll
    for (int rr = 0; rr < ROWS_PER_THREAD; ++rr) {
        load_row6(img, rbase + rr + 1, tx, win[(rr + 2) % 3]);

        const float* T  = win[rr % 3];
        const float* M  = win[(rr + 1) % 3];
        const float* Bt = win[(rr + 2) % 3];

        float4 r;
        r.x = w00*T[0]; r.x = fmaf(w01,T[1],r.x); r.x = fmaf(w02,T[2],r.x);
        r.x = fmaf(w10,M[0],r.x); r.x = fmaf(w11,M[1],r.x); r.x = fmaf(w12,M[2],r.x);
        r.x = fmaf(w20,Bt[0],r.x); r.x = fmaf(w21,Bt[1],r.x); r.x = fmaf(w22,Bt[2],r.x);

        r.y = w00*T[1]; r.y = fmaf(w01,T[2],r.y); r.y = fmaf(w02,T[3],r.y);
        r.y = fmaf(w10,M[1],r.y); r.y = fmaf(w11,M[2],r.y); r.y = fmaf(w12,M[3],r.y);
        r.y = fmaf(w20,Bt[1],r.y); r.y = fmaf(w21,Bt[2],r.y); r.y = fmaf(w22,Bt[3],r.y);

        r.z = w00*T[2]; r.z = fmaf(w01,T[3],r.z); r.z = fmaf(w02,T[4],r.z);
        r.z = fmaf(w10,M[2],r.z); r.z = fmaf(w11,M[3],r.z); r.z = fmaf(w12,M[4],r.z);
        r.z = fmaf(w20,Bt[2],r.z); r.z = fmaf(w21,Bt[3],r.z); r.z = fmaf(w22,Bt[4],r.z);

        r.w = w00*T[3]; r.w = fmaf(w01,T[4],r.w); r.w = fmaf(w02,T[5],r.w);
        r.w = fmaf(w10,M[3],r.w); r.w = fmaf(w11,M[4],r.w); r.w = fmaf(w12,M[5],r.w);
        r.w = fmaf(w20,Bt[3],r.w); r.w = fmaf(w21,Bt[4],r.w); r.w = fmaf(w22,Bt[5],r.w);

        __stcs((float4*)(o + (size_t)(rbase + rr) * WW + 4 * tx), r);
    }

    // last conv block resets flags for next graph replay
    if (tid == 0) {
        unsigned int old = atomicAdd(&g_done.v, 1u);
        if (old == CONV_BLOCKS - 1u) {
            g_ready.v = 0u; g_sm.v = 0u; g_done.v = 0u;
            __threadfence();
        }
    }
}

// ---------------------------------------------------------------------------
extern "C" void kernel_launch(void* const* d_in, const int* in_sizes, int n_in,
                              void* d_out, int out_size) {
    const float* Fd = (const float*)d_in[0];
    const float* Fc = (const float*)d_in[1];
    const float* W1 = (const float*)d_in[2];
    const float* b1 = (const float*)d_in[3];
    const float* W2 = (const float*)d_in[4];
    const float* b2 = (const float*)d_in[5];
    float* out = (float*)d_out;

    const int write_tail = ((size_t)out_size >= FOUT_ELEMS + (size_t)B_SZ * CKK) ? 1 : 0;
    float* kw_tail = out + FOUT_ELEMS;

    EKG_fused<<<TOTAL_BLOCKS, 256>>>(Fd, Fc, W1, b1, W2, b2, out, kw_tail, write_tail);
}

// round 13
// speedup vs baseline: 1.4797x; 1.0862x over previous
#include <cuda_runtime.h>
#include <cuda_bf16.h>
#include <math.h>

#define B_SZ   16
#define C_IN   64
#define HH     256
#define WW     256
#define CKK    576
#define FC_DIM 512
#define IMG_PIX (HH * WW)
#define N_IMG  (B_SZ * C_IN)
#define FOUT_ELEMS ((size_t)N_IMG * IMG_PIX)

// Partials (deterministic fixed-order summation)
__device__ float g_p1[8][B_SZ * CKK];   // layer1 partials per 64-i-chunk (ic0 includes b1)
__device__ float g_p2[9][B_SZ * CKK];   // layer2 partials per 64-i-chunk (ic0 includes b2)
__device__ float g_kw[B_SZ * CKK];      // softmaxed kernel weights

// ---------------------------------------------------------------------------
// Layer 1: 24 blocks = (jt 0..2) x (ic 0..7). Block: 192 threads.
// Stage W1 tile [64 x 192] (float4, read once grid-wide) + Fc slice [16 x 64].
// Each thread: one j column, acc over all 16 batches.
// ---------------------------------------------------------------------------
__global__ __launch_bounds__(192) void EKG_mlp1(
    const float* __restrict__ Fc,
    const float* __restrict__ W1, const float* __restrict__ b1)
{
    __shared__ float sw[64 * 192];    // 48KB weight tile
    __shared__ float sfc[16 * 64];    // 4KB input slice

    const int jt = blockIdx.x;        // 0..2
    const int ic = blockIdx.y;        // 0..7
    const int i0 = ic * 64;
    const int tid = threadIdx.x;
    const int j  = jt * 192 + tid;

    // Stage W1 tile: rows i0..i0+63, cols jt*192..+191, as float4.
    {
        const float4* __restrict__ W1_4 = (const float4*)W1;
        float4* sw4 = (float4*)sw;
        #pragma unroll
        for (int q = tid; q < 64 * 48; q += 192) {
            const int r = q / 48, c = q % 48;
            sw4[r * 48 + c] = __ldg(W1_4 + (size_t)(i0 + r) * (CKK / 4) + jt * 48 + c);
        }
    }
    // Stage Fc slice [16 x 64] as float4.
    {
        const float4* __restrict__ Fc4 = (const float4*)Fc;
        float4* sfc4 = (float4*)sfc;
        #pragma unroll
        for (int q = tid; q < 256; q += 192) {
            const int b = q >> 4, c = q & 15;
            sfc4[b * 16 + c] = __ldg(Fc4 + b * (FC_DIM / 4) + ic * 16 + c);
        }
    }
    __syncthreads();

    float acc[16];
    #pragma unroll
    for (int b = 0; b < 16; ++b) acc[b] = 0.f;
    #pragma unroll 4
    for (int il = 0; il < 64; ++il) {
        const float w = sw[il * 192 + tid];
        #pragma unroll
        for (int b = 0; b < 16; ++b)
            acc[b] = fmaf(sfc[b * 64 + il], w, acc[b]);
    }

    const float bias = (ic == 0) ? b1[j] : 0.0f;
    #pragma unroll
    for (int b = 0; b < 16; ++b)
        g_p1[ic][b * CKK + j] = acc[b] + bias;
}

// ---------------------------------------------------------------------------
// Layer 2: 27 blocks = (jt 0..2) x (ic 0..8). Same structure over W2.
// Input h = relu(sum of 8 layer-1 partials).
// ---------------------------------------------------------------------------
__global__ __launch_bounds__(192) void EKG_mlp2(
    const float* __restrict__ W2, const float* __restrict__ b2)
{
    __shared__ float sw[64 * 192];
    __shared__ float sfc[16 * 64];

    const int jt = blockIdx.x;        // 0..2
    const int ic = blockIdx.y;        // 0..8
    const int i0 = ic * 64;
    const int tid = threadIdx.x;
    const int j  = jt * 192 + tid;

    {
        const float4* __restrict__ W2_4 = (const float4*)W2;
        float4* sw4 = (float4*)sw;
        #pragma unroll
        for (int q = tid; q < 64 * 48; q += 192) {
            const int r = q / 48, c = q % 48;
            sw4[r * 48 + c] = __ldg(W2_4 + (size_t)(i0 + r) * (CKK / 4) + jt * 48 + c);
        }
    }
    // h slice [16 x 64]: relu(sum of 8 partials)
    #pragma unroll
    for (int q = tid; q < 1024; q += 192) {
        const int b = q >> 6, il = q & 63;
        const int idx = b * CKK + i0 + il;
        float h = (((g_p1[0][idx] + g_p1[1][idx]) + (g_p1[2][idx] + g_p1[3][idx])) +
                   ((g_p1[4][idx] + g_p1[5][idx]) + (g_p1[6][idx] + g_p1[7][idx])));
        sfc[q] = fmaxf(h, 0.0f);
    }
    __syncthreads();

    float acc[16];
    #pragma unroll
    for (int b = 0; b < 16; ++b) acc[b] = 0.f;
    #pragma unroll 4
    for (int il = 0; il < 64; ++il) {
        const float w = sw[il * 192 + tid];
        #pragma unroll
        for (int b = 0; b < 16; ++b)
            acc[b] = fmaf(sfc[b * 64 + il], w, acc[b]);
    }

    const float bias = (ic == 0) ? b2[j] : 0.0f;
    #pragma unroll
    for (int b = 0; b < 16; ++b)
        g_p2[ic][b * CKK + j] = acc[b] + bias;
}

// ---------------------------------------------------------------------------
// Softmax over 576 (summing the 9 logit partials). grid 16, block 576.
// ---------------------------------------------------------------------------
__global__ __launch_bounds__(CKK) void EKG_softmax(
    float* __restrict__ kw_tail, int write_tail)
{
    __shared__ float red[32];
    __shared__ float bcast;
    const int b = blockIdx.x;
    const int j = threadIdx.x;
    const int lane = j & 31;
    const int wid  = j >> 5;
    const int idx  = b * CKK + j;

    const float logit = ((((g_p2[0][idx] + g_p2[1][idx]) + (g_p2[2][idx] + g_p2[3][idx])) +
                          ((g_p2[4][idx] + g_p2[5][idx]) + (g_p2[6][idx] + g_p2[7][idx]))) +
                         g_p2[8][idx]);

    float m = logit;
    #pragma unroll
    for (int o = 16; o > 0; o >>= 1)
        m = fmaxf(m, __shfl_xor_sync(0xffffffffu, m, o));
    if (lane == 0) red[wid] = m;
    __syncthreads();
    if (wid == 0) {
        float v = (lane < 18) ? red[lane] : -INFINITY;
        #pragma unroll
        for (int o = 16; o > 0; o >>= 1)
            v = fmaxf(v, __shfl_xor_sync(0xffffffffu, v, o));
        if (lane == 0) bcast = v;
    }
    __syncthreads();
    const float e = expf(logit - bcast);

    float s = e;
    #pragma unroll
    for (int o = 16; o > 0; o >>= 1)
        s += __shfl_xor_sync(0xffffffffu, s, o);
    __syncthreads();
    if (lane == 0) red[wid] = s;
    __syncthreads();
    if (wid == 0) {
        float v = (lane < 18) ? red[lane] : 0.0f;
        #pragma unroll
        for (int o = 16; o > 0; o >>= 1)
            v += __shfl_xor_sync(0xffffffffu, v, o);
        if (lane == 0) bcast = v;
    }
    __syncthreads();

    const float kw = e / bcast;
    g_kw[idx] = kw;
    if (write_tail) kw_tail[idx] = kw;
}

// ---------------------------------------------------------------------------
// Depthwise 3x3 conv, reflect pad, no smem (measured-best, unchanged).
// Block 256: tx 0..63 (float4 col group), ty 0..3 (8-row strip). Grid (8,1024).
// ---------------------------------------------------------------------------
#define ROWS_PER_BLOCK 32
#define ROWS_PER_THREAD 8

__device__ __forceinline__ void load_row6(
    const float* __restrict__ img, int gr, int tx, float* __restrict__ w)
{
    gr = (gr < 0) ? 1 : ((gr > HH - 1) ? (2 * HH - 2 - gr) : gr);
    const float* rowp = img + gr * WW;
    const float4 q = __ldg((const float4*)rowp + tx);
    w[1] = q.x; w[2] = q.y; w[3] = q.z; w[4] = q.w;
    w[0] = (tx == 0)      ? q.y : __ldg(rowp + 4 * tx - 1);
    w[5] = (tx == WW/4-1) ? q.z : __ldg(rowp + 4 * tx + 4);
}

__global__ __launch_bounds__(256) void EKG_conv_kernel(
    const float* __restrict__ Fd,
    float* __restrict__ out)
{
    const int bc   = blockIdx.y;
    const int tid  = threadIdx.x;
    const int tx   = tid & 63;
    const int ty   = tid >> 6;
    const int rbase = blockIdx.x * ROWS_PER_BLOCK + ty * ROWS_PER_THREAD;

    const float* __restrict__ img = Fd  + (size_t)bc * IMG_PIX;
    float*       __restrict__ o   = out + (size_t)bc * IMG_PIX;

    const float* kwp = g_kw + bc * 9;
    const float w00 = __ldg(kwp+0), w01 = __ldg(kwp+1), w02 = __ldg(kwp+2);
    const float w10 = __ldg(kwp+3), w11 = __ldg(kwp+4), w12 = __ldg(kwp+5);
    const float w20 = __ldg(kwp+6), w21 = __ldg(kwp+7), w22 = __ldg(kwp+8);

    float win[3][6];
    load_row6(img, rbase - 1, tx, win[0]);
    load_row6(img, rbase + 0, tx, win[1]);

    #pragma unroll
    for (int rr = 0; rr < ROWS_PER_THREAD; ++rr) {
        load_row6(img, rbase + rr + 1, tx, win[(rr + 2) % 3]);

        const float* T  = win[rr % 3];
        const float* M  = win[(rr + 1) % 3];
        const float* Bt = win[(rr + 2) % 3];

        float4 r;
        r.x = w00*T[0]; r.x = fmaf(w01,T[1],r.x); r.x = fmaf(w02,T[2],r.x);
        r.x = fmaf(w10,M[0],r.x); r.x = fmaf(w11,M[1],r.x); r.x = fmaf(w12,M[2],r.x);
        r.x = fmaf(w20,Bt[0],r.x); r.x = fmaf(w21,Bt[1],r.x); r.x = fmaf(w22,Bt[2],r.x);

        r.y = w00*T[1]; r.y = fmaf(w01,T[2],r.y); r.y = fmaf(w02,T[3],r.y);
        r.y = fmaf(w10,M[1],r.y); r.y = fmaf(w11,M[2],r.y); r.y = fmaf(w12,M[3],r.y);
        r.y = fmaf(w20,Bt[1],r.y); r.y = fmaf(w21,Bt[2],r.y); r.y = fmaf(w22,Bt[3],r.y);

        r.z = w00*T[2]; r.z = fmaf(w01,T[3],r.z); r.z = fmaf(w02,T[4],r.z);
        r.z = fmaf(w10,M[2],r.z); r.z = fmaf(w11,M[3],r.z); r.z = fmaf(w12,M[4],r.z);
        r.z = fmaf(w20,Bt[2],r.z); r.z = fmaf(w21,Bt[3],r.z); r.z = fmaf(w22,Bt[4],r.z);

        r.w = w00*T[3]; r.w = fmaf(w01,T[4],r.w); r.w = fmaf(w02,T[5],r.w);
        r.w = fmaf(w10,M[3],r.w); r.w = fmaf(w11,M[4],r.w); r.w = fmaf(w12,M[5],r.w);
        r.w = fmaf(w20,Bt[3],r.w); r.w = fmaf(w21,Bt[4],r.w); r.w = fmaf(w22,Bt[5],r.w);

        __stcs((float4*)(o + (size_t)(rbase + rr) * WW + 4 * tx), r);
    }
}

// ---------------------------------------------------------------------------
extern "C" void kernel_launch(void* const* d_in, const int* in_sizes, int n_in,
                              void* d_out, int out_size) {
    const float* Fd = (const float*)d_in[0];
    const float* Fc = (const float*)d_in[1];
    const float* W1 = (const float*)d_in[2];
    const float* b1 = (const float*)d_in[3];
    const float* W2 = (const float*)d_in[4];
    const float* b2 = (const float*)d_in[5];
    float* out = (float*)d_out;

    const int write_tail = ((size_t)out_size >= FOUT_ELEMS + (size_t)B_SZ * CKK) ? 1 : 0;
    float* kw_tail = out + FOUT_ELEMS;

    EKG_mlp1<<<dim3(3, 8), 192>>>(Fc, W1, b1);
    EKG_mlp2<<<dim3(3, 9), 192>>>(W2, b2);
    EKG_softmax<<<B_SZ, CKK>>>(kw_tail, write_tail);

    dim3 grid(HH / ROWS_PER_BLOCK, N_IMG);
    EKG_conv_kernel<<<grid, 256>>>(Fd, out);
}